// round 10
// baseline (speedup 1.0000x reference)
#include <cuda_runtime.h>
#include <math.h>
#include <stdint.h>

#define B_ROWS   131072
#define NM       6
#define NP       30
#define WARPS    8
#define GRID     2048
#define RPW      (B_ROWS / (GRID * WARPS))   // 8 rows per warp
#define STRIDE   (GRID * WARPS)
#define STAGES   3

// 0 num_cls, 1 mgn_sum, 2 reg_loss, 3 num_reg,
// 4 a6x, 5 a6y, 6 f6x, 7 f6y, 8 a1x, 9 a1y, 10 f1x, 11 f1y
__device__ double g_acc[12];
__device__ unsigned int g_done;

struct __align__(16) Stage {
    float reg[360];   // 1440 B: one row of reg [6,30,2]
    float gt[64];     // 256 B: 60 used
};

__device__ __forceinline__ float warp_sum(float v) {
#pragma unroll
    for (int o = 16; o; o >>= 1) v += __shfl_xor_sync(0xffffffffu, v, o);
    return v;
}

__device__ __forceinline__ void cp16(uint32_t dst, const void* src) {
    asm volatile("cp.async.cg.shared.global [%0], [%1], 16;\n" :: "r"(dst), "l"(src));
}
__device__ __forceinline__ void cp_commit() {
    asm volatile("cp.async.commit_group;\n" ::: "memory");
}
__device__ __forceinline__ void cp_wait2() {
    asm volatile("cp.async.wait_group 2;\n" ::: "memory");
}

// order-preserving float->uint key
__device__ __forceinline__ unsigned fkey(float f) {
    unsigned b = __float_as_uint(f);
    return (b & 0x80000000u) ? ~b : (b | 0x80000000u);
}

__global__ void __launch_bounds__(256, 5) loss_main(
    const float* __restrict__ reg,
    const float* __restrict__ cls,
    const float* __restrict__ gt,
    const void*  __restrict__ has,
    float* __restrict__ out)
{
    __shared__ Stage st[WARPS][STAGES];
    __shared__ double blk[12];

    const int lane = threadIdx.x & 31;
    const int warp = threadIdx.x >> 5;
    if (threadIdx.x < 12) blk[threadIdx.x] = 0.0;
    __syncthreads();

    // detect storage width of bool array `has`
    const unsigned w0 = *((const unsigned*)has);
    const int hmode = (w0 == 0x3F800000u) ? 2 : ((w0 == 1u) ? 1 : 0);

    const int wg = blockIdx.x * WARPS + warp;

    float a_numcls = 0.f, a_mgn = 0.f, a_regl = 0.f, a_numreg = 0.f;
    float a6x = 0.f, a6y = 0.f, f6x = 0.f, f6y = 0.f;
    float a1x = 0.f, a1y = 0.f, f1x = 0.f, f1y = 0.f;

    float hb[STAGES] = {0.f, 0.f, 0.f};
    float cb[STAGES] = {0.f, 0.f, 0.f};

    uint32_t sbase[STAGES];
#pragma unroll
    for (int i = 0; i < STAGES; i++)
        sbase[i] = (uint32_t)__cvta_generic_to_shared(&st[warp][i]);

    auto prefetch = [&](int it, int slot) {
        if (it < RPW) {
            const int row = wg + it * STRIDE;
            const uint32_t sb = sbase[slot];
            const char* rsrc = (const char*)(reg + (size_t)row * 360);
            cp16(sb + lane * 16,          rsrc + lane * 16);
            cp16(sb + (lane + 32) * 16,   rsrc + (lane + 32) * 16);
            if (lane < 26)
                cp16(sb + (lane + 64) * 16, rsrc + (lane + 64) * 16);
            if (lane < 15)
                cp16(sb + 1440 + lane * 16,
                     (const char*)(gt + (size_t)row * 60) + lane * 16);
            if (lane < NP) {
                size_t hidx = (size_t)row * NP + lane;
                if (hmode == 0)      hb[slot] = ((const unsigned char*)has)[hidx] ? 1.f : 0.f;
                else if (hmode == 1) hb[slot] = ((const int*)has)[hidx] ? 1.f : 0.f;
                else                 hb[slot] = (((const float*)has)[hidx] != 0.f) ? 1.f : 0.f;
            }
            if (lane < NM) cb[slot] = cls[(size_t)row * NM + lane];
        }
        cp_commit();
    };

    // scalar pre-pass for row `it`: last/valid from hb (already in regs),
    // plus direct LDG of reg[row, m, last] for lanes<NM (consumed next iter)
    auto scalar_ahead = [&](int it, int slot, int& last_o, float& validf_o,
                            float2& rl_o) {
        const float hvv = (lane < NP) ? hb[slot] : 0.f;
        const unsigned b = __ballot_sync(0xffffffffu, (lane < NP) && (hvv > 0.f));
        last_o   = b ? (31 - __clz(b)) : (NP - 1);
        validf_o = b ? 1.0f : 0.0f;
        if (it < RPW) {
            if (lane == 0) a_numreg += validf_o * (float)__popc(b);
            if (lane < NM) {
                const int row = wg + it * STRIDE;
                rl_o = *(const float2*)(reg + (size_t)row * 360
                                        + lane * 60 + 2 * last_o);
            }
        }
    };

    prefetch(0, 0);
    prefetch(1, 1);

    int    last_cur;  float validf_cur;  float2 rl_cur = make_float2(0.f, 0.f);
    scalar_ahead(0, 0, last_cur, validf_cur, rl_cur);   // stalls once on hb[0]

#pragma unroll
    for (int it = 0; it < RPW; ++it) {
        const int slot = it % STAGES;
        prefetch(it + 2, (it + 2) % STAGES);   // keep 2 rows in flight

        // scalar pre-pass for NEXT row (hb[it+1] is ready; rl LDG hides 1 iter)
        int last_nxt; float validf_nxt; float2 rl_nxt = make_float2(0.f, 0.f);
        scalar_ahead(it + 1, (it + 1) % STAGES, last_nxt, validf_nxt, rl_nxt);

        cp_wait2();                            // row `it` smem complete
        __syncwarp();

        Stage& S = st[warp][slot];
        const int  last   = last_cur;
        const float validf = validf_cur;
        const bool valid  = validf != 0.f;

        // issue gl broadcast LDS immediately (address known from pre-pass)
        const float2 gl = *(const float2*)&S.gt[2 * last];

        const float hv = (lane < NP) ? hb[slot] : 0.f;

        // ---- gt for lane t + clamped neighbors ----
        const int t = (lane < NP) ? lane : (NP - 1);
        const float2 gv = *(const float2*)&S.gt[2 * t];
        const float gx = gv.x, gy = gv.y;
        const float2 gp = *(const float2*)&S.gt[2 * ((t > 0) ? t - 1 : 0)];
        const float2 gn = *(const float2*)&S.gt[2 * ((t < NP - 1) ? t + 1 : NP - 1)];

        // moving flag (broadcast LDS)
        const float2 g0 = *(const float2*)&S.gt[0];
        const float2 gL = *(const float2*)&S.gt[2 * (NP - 1)];
        const float mdx = g0.x - gL.x, mdy = g0.y - gL.y;
        const bool moving = (mdx * mdx + mdy * mdy) > 4.0f;

        // ---- per-mode distance at last point (rl register-resident) ----
        float dstm = 1e30f, myc = 0.f;
        if (lane < NM) {
            float ddx = rl_cur.x - gl.x, ddy = rl_cur.y - gl.y;
            dstm = sqrtf(ddx * ddx + ddy * ddy);
            myc  = cb[slot];
        }

        // ---- argmin(dist) / argmax(cls) via HW REDUX ----
        const unsigned dbits = __float_as_uint(dstm);
        const unsigned dmin  = __reduce_min_sync(0xffffffffu, dbits);
        const unsigned mmask = __ballot_sync(0xffffffffu, dbits == dmin);
        const int   min_idx  = __ffs(mmask) - 1;
        const float min_dist = __uint_as_float(dmin);

        const unsigned ckey = (lane < NM) ? fkey(myc) : 0u;
        const unsigned cmax = __reduce_max_sync(0xffffffffu, ckey);
        const unsigned tmask = __ballot_sync(0xffffffffu, ckey == cmax);
        const int top1 = __ffs(tmask) - 1;

        const float cls_min = __shfl_sync(0xffffffffu, myc, min_idx);
        if (lane < NM) {
            float mgn = cls_min - myc;
            bool m01 = (min_dist < 2.0f) && ((dstm - min_dist) > 0.2f) && valid;
            if (m01 && (mgn < 0.2f)) { a_numcls += 1.0f; a_mgn += mgn; }
        }

        // ---- heading (trig-free, endpoint via select) ----
        float c = 1.f, s = 0.f;
        if (moving && lane < NP) {
            float fdx = gn.x - gx, fdy = gn.y - gy;
            float bdx = gx - gp.x, bdy = gy - gp.y;
            float fr = fdx * fdx + fdy * fdy;
            float br = bdx * bdx + bdy * bdy;
            float cf = 1.f, sf = 0.f, cbw = 1.f, sbw = 0.f;
            if (fr > 0.f) { float inv = rsqrtf(fr); cf = fdx * inv; sf = fdy * inv; }
            if (br > 0.f) { float inv = rsqrtf(br); cbw = bdx * inv; sbw = bdy * inv; }
            if (lane == 0)      { cbw = cf;  sbw = sf; }
            if (lane == NP - 1) { cf = cbw;  sf = sbw; }

            float hx = cf + cbw, hy = sf + sbw;
            float dxx = cf - cbw, dyy = sf - sbw;
            float h2 = hx * hx + hy * hy;
            float d2 = dxx * dxx + dyy * dyy;
            if (h2 >= d2) { float inv = rsqrtf(h2); c = hx * inv;  s = -(hy * inv); }
            else          { float inv = rsqrtf(d2); c = dyy * inv; s = dxx * inv; }
        }

        // ---- main sweep: lane = t; per-row sums hoist lane==29 predication ----
        if (lane < NP) {
            const float w = hv * validf;
            float r6x = 0.f, r6y = 0.f, r1x = 0.f, r1y = 0.f;
#pragma unroll
            for (int k = 0; k < NM; k++) {
                float2 rv = *(const float2*)&S.reg[k * 60 + 2 * lane];
                float dx = fabsf(gx - rv.x);
                float dy = fabsf(gy - rv.y);
                float ex = fabsf(c * dx - s * dy);
                float ey = fabsf(s * dx + c * dy);
                r6x += ex; r6y += ey;
                if (k == top1) { r1x = ex; r1y = ey; }   // warp-uniform
                if (k == min_idx) {                      // warp-uniform
                    float slx = (dx < 1.f) ? 0.5f * dx * dx : dx - 0.5f;
                    float sly = (dy < 1.f) ? 0.5f * dy * dy : dy - 0.5f;
                    a_regl += (slx + sly) * w;
                }
            }
            a6x += r6x; a6y += r6y;
            a1x += r1x; a1y += r1y;
            if (lane == NP - 1) {
                f6x += r6x; f6y += r6y;
                f1x += r1x; f1y += r1y;
            }
        }
        __syncwarp();   // WAR: this stage gets rewritten 3 iterations later

        last_cur = last_nxt; validf_cur = validf_nxt; rl_cur = rl_nxt;
    }

    // ---- reduction ----
    a_numcls = warp_sum(a_numcls);
    a_mgn    = warp_sum(a_mgn);
    a_regl   = warp_sum(a_regl);
    a_numreg = warp_sum(a_numreg);
    a6x = warp_sum(a6x); a6y = warp_sum(a6y);
    f6x = warp_sum(f6x); f6y = warp_sum(f6y);
    a1x = warp_sum(a1x); a1y = warp_sum(a1y);
    f1x = warp_sum(f1x); f1y = warp_sum(f1y);

    if (lane == 0) {
        atomicAdd(&blk[0],  (double)a_numcls);
        atomicAdd(&blk[1],  (double)a_mgn);
        atomicAdd(&blk[2],  (double)a_regl);
        atomicAdd(&blk[3],  (double)a_numreg);
        atomicAdd(&blk[4],  (double)a6x);
        atomicAdd(&blk[5],  (double)a6y);
        atomicAdd(&blk[6],  (double)f6x);
        atomicAdd(&blk[7],  (double)f6y);
        atomicAdd(&blk[8],  (double)a1x);
        atomicAdd(&blk[9],  (double)a1y);
        atomicAdd(&blk[10], (double)f1x);
        atomicAdd(&blk[11], (double)f1y);
    }
    __syncthreads();
    if (threadIdx.x < 12) {
        atomicAdd(&g_acc[threadIdx.x], blk[threadIdx.x]);
        __threadfence();
    }
    __syncthreads();

    if (threadIdx.x == 0) {
        unsigned done = atomicAdd(&g_done, 1u);
        if (done == GRID - 1) {
            __threadfence();
            double acc[12];
#pragma unroll
            for (int i = 0; i < 12; i++) acc[i] = *((volatile double*)&g_acc[i]);

            double num_cls  = acc[0];
            double mgn_sum  = acc[1];
            double reg_loss = acc[2];
            double num_reg  = acc[3];
            double cls_loss = 0.2 * num_cls - mgn_sum;
            double loss = cls_loss / (num_cls + 1e-10) + reg_loss / (num_reg + 1e-10);
            out[0]  = (float)loss;
            out[1]  = (float)cls_loss;
            out[2]  = (float)num_cls;
            out[3]  = (float)reg_loss;
            out[4]  = (float)num_reg;
            out[5]  = (float)acc[4];
            out[6]  = (float)acc[5];
            out[7]  = (float)acc[6];
            out[8]  = (float)acc[7];
            out[9]  = (float)(6.0 * (double)B_ROWS * 30.0);
            out[10] = (float)(6.0 * (double)B_ROWS);
            out[11] = (float)acc[8];
            out[12] = (float)acc[9];
            out[13] = (float)acc[10];
            out[14] = (float)acc[11];
            out[15] = (float)((double)B_ROWS * 30.0);
            out[16] = (float)B_ROWS;

#pragma unroll
            for (int i = 0; i < 12; i++) *((volatile double*)&g_acc[i]) = 0.0;
            __threadfence();
            atomicExch(&g_done, 0u);
        }
    }
}

extern "C" void kernel_launch(void* const* d_in, const int* in_sizes, int n_in,
                              void* d_out, int out_size) {
    const float* reg = nullptr;
    const float* cls = nullptr;
    const float* gt  = nullptr;
    const void*  has = nullptr;
    for (int i = 0; i < n_in; i++) {
        long long n = in_sizes[i];
        if (n == (long long)B_ROWS * NM * NP * 2)      reg = (const float*)d_in[i];
        else if (n == (long long)B_ROWS * NP * 2)      gt  = (const float*)d_in[i];
        else if (n == (long long)B_ROWS * NP)          has = d_in[i];
        else if (n == (long long)B_ROWS * NM)          cls = (const float*)d_in[i];
    }
    float* out = (float*)d_out;

    loss_main<<<GRID, 256>>>(reg, cls, gt, has, out);
}

// round 11
// speedup vs baseline: 1.0608x; 1.0608x over previous
#include <cuda_runtime.h>
#include <math.h>
#include <stdint.h>

#define B_ROWS   131072
#define NM       6
#define NP       30
#define WARPS    8
#define GRID     2048
#define RPW      (B_ROWS / (GRID * WARPS))   // 8 rows per warp
#define STRIDE   (GRID * WARPS)
#define STAGES   4

// 0 num_cls, 1 mgn_sum, 2 reg_loss, 3 num_reg,
// 4 a6x, 5 a6y, 6 f6x, 7 f6y, 8 a1x, 9 a1y, 10 f1x, 11 f1y
__device__ double g_acc[12];
__device__ unsigned int g_done;

struct __align__(16) Stage {
    float reg[360];   // 1440 B: one row of reg [6,30,2]
    float gt[64];     // 256 B: 60 used
};

__device__ __forceinline__ float warp_sum(float v) {
#pragma unroll
    for (int o = 16; o; o >>= 1) v += __shfl_xor_sync(0xffffffffu, v, o);
    return v;
}

__device__ __forceinline__ void cp16(uint32_t dst, const void* src) {
    asm volatile("cp.async.cg.shared.global [%0], [%1], 16;\n" :: "r"(dst), "l"(src));
}
__device__ __forceinline__ void cp_commit() {
    asm volatile("cp.async.commit_group;\n" ::: "memory");
}
__device__ __forceinline__ void cp_wait2() {
    asm volatile("cp.async.wait_group 2;\n" ::: "memory");
}

// order-preserving float->uint key
__device__ __forceinline__ unsigned fkey(float f) {
    unsigned b = __float_as_uint(f);
    return (b & 0x80000000u) ? ~b : (b | 0x80000000u);
}

__global__ void __launch_bounds__(256, 4) loss_main(
    const float* __restrict__ reg,
    const float* __restrict__ cls,
    const float* __restrict__ gt,
    const void*  __restrict__ has,
    float* __restrict__ out)
{
    extern __shared__ Stage st[];            // [WARPS][STAGES] flattened
    __shared__ double blk[12];

    const int lane = threadIdx.x & 31;
    const int warp = threadIdx.x >> 5;
    if (threadIdx.x < 12) blk[threadIdx.x] = 0.0;
    __syncthreads();

    // detect storage width of bool array `has`
    const unsigned w0 = *((const unsigned*)has);
    const int hmode = (w0 == 0x3F800000u) ? 2 : ((w0 == 1u) ? 1 : 0);

    const int wg = blockIdx.x * WARPS + warp;

    float a_numcls = 0.f, a_mgn = 0.f, a_regl = 0.f, a_numreg = 0.f;
    float a6x = 0.f, a6y = 0.f, f6x = 0.f, f6y = 0.f;
    float a1x = 0.f, a1y = 0.f, f1x = 0.f, f1y = 0.f;

    float hb[STAGES] = {0.f, 0.f, 0.f, 0.f};
    float cb[STAGES] = {0.f, 0.f, 0.f, 0.f};

    uint32_t sbase[STAGES];
#pragma unroll
    for (int i = 0; i < STAGES; i++)
        sbase[i] = (uint32_t)__cvta_generic_to_shared(&st[warp * STAGES + i]);

    auto prefetch = [&](int it, int slot) {
        if (it < RPW) {
            const int row = wg + it * STRIDE;
            const uint32_t sb = sbase[slot];
            const char* rsrc = (const char*)(reg + (size_t)row * 360);
            cp16(sb + lane * 16,          rsrc + lane * 16);
            cp16(sb + (lane + 32) * 16,   rsrc + (lane + 32) * 16);
            if (lane < 26)
                cp16(sb + (lane + 64) * 16, rsrc + (lane + 64) * 16);
            if (lane < 15)
                cp16(sb + 1440 + lane * 16,
                     (const char*)(gt + (size_t)row * 60) + lane * 16);
            if (lane < NP) {
                size_t hidx = (size_t)row * NP + lane;
                if (hmode == 0)      hb[slot] = ((const unsigned char*)has)[hidx] ? 1.f : 0.f;
                else if (hmode == 1) hb[slot] = ((const int*)has)[hidx] ? 1.f : 0.f;
                else                 hb[slot] = (((const float*)has)[hidx] != 0.f) ? 1.f : 0.f;
            }
            if (lane < NM) cb[slot] = cls[(size_t)row * NM + lane];
        }
        cp_commit();
    };

    // full single-row body (R9 structure), reading staged smem slot
    auto process_row = [&](int slot) {
        Stage& S = st[warp * STAGES + slot];

        const float hv = (lane < NP) ? hb[slot] : 0.f;
        const unsigned bal = __ballot_sync(0xffffffffu, (lane < NP) && (hv > 0.f));
        const int  last   = bal ? (31 - __clz(bal)) : (NP - 1);
        const bool valid  = (bal != 0u);
        const float validf = valid ? 1.0f : 0.0f;
        if (lane == 0) a_numreg += validf * (float)__popc(bal);

        const int t = (lane < NP) ? lane : (NP - 1);
        const float2 gv = *(const float2*)&S.gt[2 * t];
        const float gx = gv.x, gy = gv.y;
        const float2 gp = *(const float2*)&S.gt[2 * ((t > 0) ? t - 1 : 0)];
        const float2 gn = *(const float2*)&S.gt[2 * ((t < NP - 1) ? t + 1 : NP - 1)];

        const float2 g0 = *(const float2*)&S.gt[0];
        const float2 gL = *(const float2*)&S.gt[2 * (NP - 1)];
        const float mdx = g0.x - gL.x, mdy = g0.y - gL.y;
        const bool moving = (mdx * mdx + mdy * mdy) > 4.0f;

        float c = 1.f, s = 0.f;
        if (moving && lane < NP) {
            float fdx = gn.x - gx, fdy = gn.y - gy;
            float bdx = gx - gp.x, bdy = gy - gp.y;
            float fr = fdx * fdx + fdy * fdy;
            float br = bdx * bdx + bdy * bdy;
            float cf = 1.f, sf = 0.f, cbw = 1.f, sbw = 0.f;
            if (fr > 0.f) { float inv = rsqrtf(fr); cf = fdx * inv; sf = fdy * inv; }
            if (br > 0.f) { float inv = rsqrtf(br); cbw = bdx * inv; sbw = bdy * inv; }
            if (lane == 0)      { cbw = cf;  sbw = sf; }
            if (lane == NP - 1) { cf = cbw;  sf = sbw; }

            float hx = cf + cbw, hy = sf + sbw;
            float dxx = cf - cbw, dyy = sf - sbw;
            float h2 = hx * hx + hy * hy;
            float d2 = dxx * dxx + dyy * dyy;
            if (h2 >= d2) { float inv = rsqrtf(h2); c = hx * inv;  s = -(hy * inv); }
            else          { float inv = rsqrtf(d2); c = dyy * inv; s = dxx * inv; }
        }

        const float2 gl = *(const float2*)&S.gt[2 * last];
        float dstm = 1e30f, myc = 0.f;
        if (lane < NM) {
            float2 rl = *(const float2*)&S.reg[lane * 60 + 2 * last];
            float ddx = rl.x - gl.x, ddy = rl.y - gl.y;
            dstm = sqrtf(ddx * ddx + ddy * ddy);
            myc  = cb[slot];
        }

        const unsigned dbits = __float_as_uint(dstm);
        const unsigned dmin  = __reduce_min_sync(0xffffffffu, dbits);
        const unsigned mmask = __ballot_sync(0xffffffffu, dbits == dmin);
        const int   min_idx  = __ffs(mmask) - 1;
        const float min_dist = __uint_as_float(dmin);

        const unsigned ckey = (lane < NM) ? fkey(myc) : 0u;
        const unsigned cmax = __reduce_max_sync(0xffffffffu, ckey);
        const unsigned tmask = __ballot_sync(0xffffffffu, ckey == cmax);
        const int top1 = __ffs(tmask) - 1;

        const float cls_min = __shfl_sync(0xffffffffu, myc, min_idx);
        if (lane < NM) {
            float mgn = cls_min - myc;
            bool m01 = (min_dist < 2.0f) && ((dstm - min_dist) > 0.2f) && valid;
            if (m01 && (mgn < 0.2f)) { a_numcls += 1.0f; a_mgn += mgn; }
        }

        if (lane < NP) {
            const float w = hv * validf;
            float r6x = 0.f, r6y = 0.f, r1x = 0.f, r1y = 0.f;
#pragma unroll
            for (int k = 0; k < NM; k++) {
                float2 rv = *(const float2*)&S.reg[k * 60 + 2 * lane];
                float dx = fabsf(gx - rv.x);
                float dy = fabsf(gy - rv.y);
                float ex = fabsf(c * dx - s * dy);
                float ey = fabsf(s * dx + c * dy);
                r6x += ex; r6y += ey;
                if (k == top1) { r1x = ex; r1y = ey; }   // warp-uniform
                if (k == min_idx) {                      // warp-uniform
                    float slx = (dx < 1.f) ? 0.5f * dx * dx : dx - 0.5f;
                    float sly = (dy < 1.f) ? 0.5f * dy * dy : dy - 0.5f;
                    a_regl += (slx + sly) * w;
                }
            }
            a6x += r6x; a6y += r6y;
            a1x += r1x; a1y += r1y;
            if (lane == NP - 1) {
                f6x += r6x; f6y += r6y;
                f1x += r1x; f1y += r1y;
            }
        }
    };

    prefetch(0, 0);
    prefetch(1, 1);

#pragma unroll
    for (int j = 0; j < RPW; j += 2) {
        prefetch(j + 2, (j + 2) % STAGES);
        prefetch(j + 3, (j + 3) % STAGES);
        cp_wait2();                 // rows j, j+1 complete (2 newest pending)
        __syncwarp();

        // two independent rows: ptxas interleaves their latency chains
        process_row(j % STAGES);
        process_row((j + 1) % STAGES);

        __syncwarp();               // WAR: these slots rewritten next iteration
    }

    // ---- reduction ----
    a_numcls = warp_sum(a_numcls);
    a_mgn    = warp_sum(a_mgn);
    a_regl   = warp_sum(a_regl);
    a_numreg = warp_sum(a_numreg);
    a6x = warp_sum(a6x); a6y = warp_sum(a6y);
    f6x = warp_sum(f6x); f6y = warp_sum(f6y);
    a1x = warp_sum(a1x); a1y = warp_sum(a1y);
    f1x = warp_sum(f1x); f1y = warp_sum(f1y);

    if (lane == 0) {
        atomicAdd(&blk[0],  (double)a_numcls);
        atomicAdd(&blk[1],  (double)a_mgn);
        atomicAdd(&blk[2],  (double)a_regl);
        atomicAdd(&blk[3],  (double)a_numreg);
        atomicAdd(&blk[4],  (double)a6x);
        atomicAdd(&blk[5],  (double)a6y);
        atomicAdd(&blk[6],  (double)f6x);
        atomicAdd(&blk[7],  (double)f6y);
        atomicAdd(&blk[8],  (double)a1x);
        atomicAdd(&blk[9],  (double)a1y);
        atomicAdd(&blk[10], (double)f1x);
        atomicAdd(&blk[11], (double)f1y);
    }
    __syncthreads();
    if (threadIdx.x < 12) {
        atomicAdd(&g_acc[threadIdx.x], blk[threadIdx.x]);
        __threadfence();
    }
    __syncthreads();

    if (threadIdx.x == 0) {
        unsigned done = atomicAdd(&g_done, 1u);
        if (done == GRID - 1) {
            __threadfence();
            double acc[12];
#pragma unroll
            for (int i = 0; i < 12; i++) acc[i] = *((volatile double*)&g_acc[i]);

            double num_cls  = acc[0];
            double mgn_sum  = acc[1];
            double reg_loss = acc[2];
            double num_reg  = acc[3];
            double cls_loss = 0.2 * num_cls - mgn_sum;
            double loss = cls_loss / (num_cls + 1e-10) + reg_loss / (num_reg + 1e-10);
            out[0]  = (float)loss;
            out[1]  = (float)cls_loss;
            out[2]  = (float)num_cls;
            out[3]  = (float)reg_loss;
            out[4]  = (float)num_reg;
            out[5]  = (float)acc[4];
            out[6]  = (float)acc[5];
            out[7]  = (float)acc[6];
            out[8]  = (float)acc[7];
            out[9]  = (float)(6.0 * (double)B_ROWS * 30.0);
            out[10] = (float)(6.0 * (double)B_ROWS);
            out[11] = (float)acc[8];
            out[12] = (float)acc[9];
            out[13] = (float)acc[10];
            out[14] = (float)acc[11];
            out[15] = (float)((double)B_ROWS * 30.0);
            out[16] = (float)B_ROWS;

#pragma unroll
            for (int i = 0; i < 12; i++) *((volatile double*)&g_acc[i]) = 0.0;
            __threadfence();
            atomicExch(&g_done, 0u);
        }
    }
}

extern "C" void kernel_launch(void* const* d_in, const int* in_sizes, int n_in,
                              void* d_out, int out_size) {
    const float* reg = nullptr;
    const float* cls = nullptr;
    const float* gt  = nullptr;
    const void*  has = nullptr;
    for (int i = 0; i < n_in; i++) {
        long long n = in_sizes[i];
        if (n == (long long)B_ROWS * NM * NP * 2)      reg = (const float*)d_in[i];
        else if (n == (long long)B_ROWS * NP * 2)      gt  = (const float*)d_in[i];
        else if (n == (long long)B_ROWS * NP)          has = d_in[i];
        else if (n == (long long)B_ROWS * NM)          cls = (const float*)d_in[i];
    }
    float* out = (float*)d_out;

    const size_t dyn_smem = sizeof(Stage) * WARPS * STAGES;   // 54272 B
    static int attr_set = 0;
    if (!attr_set) {
        cudaFuncSetAttribute(loss_main,
                             cudaFuncAttributeMaxDynamicSharedMemorySize,
                             (int)dyn_smem);
        attr_set = 1;
    }
    loss_main<<<GRID, 256, dyn_smem>>>(reg, cls, gt, has, (float*)out);
}

// round 12
// speedup vs baseline: 1.2171x; 1.1473x over previous
#include <cuda_runtime.h>
#include <math.h>
#include <stdint.h>

#define B_ROWS   131072
#define NM       6
#define NP       30
#define WARPS    8
#define GRID     2048
#define RPW      (B_ROWS / (GRID * WARPS))   // 8 rows per warp
#define STRIDE   (GRID * WARPS)
#define STAGES   3

// 0 num_cls, 1 mgn_sum, 2 reg_loss, 3 num_reg,
// 4 a6x, 5 a6y, 6 f6x, 7 f6y, 8 a1x, 9 a1y, 10 f1x, 11 f1y
__device__ double g_acc[12];
__device__ unsigned int g_done;

struct __align__(16) Stage {
    float reg[360];   // 1440 B: one row of reg [6,30,2]
    float gt[64];     // 256 B: 60 used
};

__device__ __forceinline__ float warp_sum(float v) {
#pragma unroll
    for (int o = 16; o; o >>= 1) v += __shfl_xor_sync(0xffffffffu, v, o);
    return v;
}

__device__ __forceinline__ void cp16(uint32_t dst, const void* src) {
    asm volatile("cp.async.cg.shared.global [%0], [%1], 16;\n" :: "r"(dst), "l"(src));
}
__device__ __forceinline__ void cp_commit() {
    asm volatile("cp.async.commit_group;\n" ::: "memory");
}
__device__ __forceinline__ void cp_wait2() {
    asm volatile("cp.async.wait_group 2;\n" ::: "memory");
}

// order-preserving float->uint key
__device__ __forceinline__ unsigned fkey(float f) {
    unsigned b = __float_as_uint(f);
    return (b & 0x80000000u) ? ~b : (b | 0x80000000u);
}

__global__ void __launch_bounds__(256, 5) loss_main(
    const float* __restrict__ reg,
    const float* __restrict__ cls,
    const float* __restrict__ gt,
    const void*  __restrict__ has,
    float* __restrict__ out)
{
    __shared__ Stage st[WARPS][STAGES];
    __shared__ double blk[12];

    const int lane = threadIdx.x & 31;
    const int warp = threadIdx.x >> 5;
    if (threadIdx.x < 12) blk[threadIdx.x] = 0.0;
    __syncthreads();

    // detect storage width of bool array `has`
    const unsigned w0 = *((const unsigned*)has);
    const int hmode = (w0 == 0x3F800000u) ? 2 : ((w0 == 1u) ? 1 : 0);

    const int wg = blockIdx.x * WARPS + warp;

    float a_numcls = 0.f, a_mgn = 0.f, a_regl = 0.f, a_numreg = 0.f;
    float a6x = 0.f, a6y = 0.f, f6x = 0.f, f6y = 0.f;
    float a1x = 0.f, a1y = 0.f, f1x = 0.f, f1y = 0.f;

    float hb[STAGES] = {0.f, 0.f, 0.f};
    float cb[STAGES] = {0.f, 0.f, 0.f};

    uint32_t sbase[STAGES];
#pragma unroll
    for (int i = 0; i < STAGES; i++)
        sbase[i] = (uint32_t)__cvta_generic_to_shared(&st[warp][i]);

    auto prefetch = [&](int it, int slot) {
        if (it < RPW) {
            const int row = wg + it * STRIDE;
            const uint32_t sb = sbase[slot];
            const char* rsrc = (const char*)(reg + (size_t)row * 360);
            cp16(sb + lane * 16,          rsrc + lane * 16);
            cp16(sb + (lane + 32) * 16,   rsrc + (lane + 32) * 16);
            if (lane < 26)
                cp16(sb + (lane + 64) * 16, rsrc + (lane + 64) * 16);
            if (lane < 15)
                cp16(sb + 1440 + lane * 16,
                     (const char*)(gt + (size_t)row * 60) + lane * 16);
            if (lane < NP) {
                size_t hidx = (size_t)row * NP + lane;
                if (hmode == 0)      hb[slot] = ((const unsigned char*)has)[hidx] ? 1.f : 0.f;
                else if (hmode == 1) hb[slot] = ((const int*)has)[hidx] ? 1.f : 0.f;
                else                 hb[slot] = (((const float*)has)[hidx] != 0.f) ? 1.f : 0.f;
            }
            if (lane < NM) cb[slot] = cls[(size_t)row * NM + lane];
        }
        cp_commit();
    };

    prefetch(0, 0);
    prefetch(1, 1);

#pragma unroll
    for (int it = 0; it < RPW; ++it) {
        const int slot = it % STAGES;
        prefetch(it + 2, (it + 2) % STAGES);   // keep 2 rows in flight
        cp_wait2();                            // row `it` complete
        __syncwarp();

        Stage& S = st[warp][slot];

        // ---- has / last / valid ----
        const float hv = (lane < NP) ? hb[slot] : 0.f;
        const unsigned bal = __ballot_sync(0xffffffffu, (lane < NP) && (hv > 0.f));
        const int  last   = bal ? (31 - __clz(bal)) : (NP - 1);
        const bool valid  = (bal != 0u);
        const float validf = valid ? 1.0f : 0.0f;
        if (lane == 0) a_numreg += validf * (float)__popc(bal);

        // ---- gt for lane t + clamped neighbors (LDS, no shuffles) ----
        const int t = (lane < NP) ? lane : (NP - 1);
        const float2 gv = *(const float2*)&S.gt[2 * t];
        const float gx = gv.x, gy = gv.y;
        const float2 gp = *(const float2*)&S.gt[2 * ((t > 0) ? t - 1 : 0)];
        const float2 gn = *(const float2*)&S.gt[2 * ((t < NP - 1) ? t + 1 : NP - 1)];

        // moving flag (broadcast LDS)
        const float2 g0 = *(const float2*)&S.gt[0];
        const float2 gL = *(const float2*)&S.gt[2 * (NP - 1)];
        const float mdx = g0.x - gL.x, mdy = g0.y - gL.y;
        const bool moving = (mdx * mdx + mdy * mdy) > 4.0f;

        // ---- heading (trig-free, endpoint via select) ----
        float c = 1.f, s = 0.f;
        if (moving && lane < NP) {
            float fdx = gn.x - gx, fdy = gn.y - gy;
            float bdx = gx - gp.x, bdy = gy - gp.y;
            float fr = fdx * fdx + fdy * fdy;
            float br = bdx * bdx + bdy * bdy;
            float cf = 1.f, sf = 0.f, cbw = 1.f, sbw = 0.f;
            if (fr > 0.f) { float inv = rsqrtf(fr); cf = fdx * inv; sf = fdy * inv; }
            if (br > 0.f) { float inv = rsqrtf(br); cbw = bdx * inv; sbw = bdy * inv; }
            if (lane == 0)      { cbw = cf;  sbw = sf; }
            if (lane == NP - 1) { cf = cbw;  sf = sbw; }

            float hx = cf + cbw, hy = sf + sbw;
            float dxx = cf - cbw, dyy = sf - sbw;
            float h2 = hx * hx + hy * hy;
            float d2 = dxx * dxx + dyy * dyy;
            if (h2 >= d2) { float inv = rsqrtf(h2); c = hx * inv;  s = -(hy * inv); }
            else          { float inv = rsqrtf(d2); c = dyy * inv; s = dxx * inv; }
        }

        // ---- per-mode distance at last point (lanes 0..5) ----
        const float2 gl = *(const float2*)&S.gt[2 * last];   // broadcast
        float dstm = 1e30f, myc = 0.f;
        if (lane < NM) {
            float2 rl = *(const float2*)&S.reg[lane * 60 + 2 * last];
            float ddx = rl.x - gl.x, ddy = rl.y - gl.y;
            dstm = sqrtf(ddx * ddx + ddy * ddy);
            myc  = cb[slot];
        }

        // ---- argmin(dist) / argmax(cls) via HW REDUX ----
        const unsigned dbits = __float_as_uint(dstm);
        const unsigned dmin  = __reduce_min_sync(0xffffffffu, dbits);
        const unsigned mmask = __ballot_sync(0xffffffffu, dbits == dmin);
        const int   min_idx  = __ffs(mmask) - 1;
        const float min_dist = __uint_as_float(dmin);

        const unsigned ckey = (lane < NM) ? fkey(myc) : 0u;
        const unsigned cmax = __reduce_max_sync(0xffffffffu, ckey);
        const unsigned tmask = __ballot_sync(0xffffffffu, ckey == cmax);
        const int top1 = __ffs(tmask) - 1;

        const float cls_min = __shfl_sync(0xffffffffu, myc, min_idx);
        if (lane < NM) {
            float mgn = cls_min - myc;
            bool m01 = (min_dist < 2.0f) && ((dstm - min_dist) > 0.2f) && valid;
            if (m01 && (mgn < 0.2f)) { a_numcls += 1.0f; a_mgn += mgn; }
        }

        // ---- main sweep: lane = t; branch-free inner loop ----
        if (lane < NP) {
            float r6x = 0.f, r6y = 0.f;
#pragma unroll
            for (int k = 0; k < NM; k++) {
                float2 rv = *(const float2*)&S.reg[k * 60 + 2 * lane];
                float dx = fabsf(gx - rv.x);
                float dy = fabsf(gy - rv.y);
                float ex = fabsf(c * dx - s * dy);
                float ey = fabsf(s * dx + c * dy);
                r6x += ex; r6y += ey;
            }
            a6x += r6x; a6y += r6y;

            // top1 mode (warp-uniform index): ade1/fde1 terms
            {
                float2 rv = *(const float2*)&S.reg[top1 * 60 + 2 * lane];
                float dx = fabsf(gx - rv.x);
                float dy = fabsf(gy - rv.y);
                float ex = fabsf(c * dx - s * dy);
                float ey = fabsf(s * dx + c * dy);
                a1x += ex; a1y += ey;
                if (lane == NP - 1) {
                    f6x += r6x; f6y += r6y;
                    f1x += ex;  f1y += ey;
                }
            }

            // min-dist mode (warp-uniform index): SmoothL1 on unrotated diffs
            {
                float2 rv = *(const float2*)&S.reg[min_idx * 60 + 2 * lane];
                float dx = fabsf(gx - rv.x);
                float dy = fabsf(gy - rv.y);
                float w  = hv * validf;
                float slx = (dx < 1.f) ? 0.5f * dx * dx : dx - 0.5f;
                float sly = (dy < 1.f) ? 0.5f * dy * dy : dy - 0.5f;
                a_regl += (slx + sly) * w;
            }
        }
        __syncwarp();   // WAR: this stage gets rewritten 3 iterations later
    }

    // ---- reduction ----
    a_numcls = warp_sum(a_numcls);
    a_mgn    = warp_sum(a_mgn);
    a_regl   = warp_sum(a_regl);
    a_numreg = warp_sum(a_numreg);
    a6x = warp_sum(a6x); a6y = warp_sum(a6y);
    f6x = warp_sum(f6x); f6y = warp_sum(f6y);
    a1x = warp_sum(a1x); a1y = warp_sum(a1y);
    f1x = warp_sum(f1x); f1y = warp_sum(f1y);

    if (lane == 0) {
        atomicAdd(&blk[0],  (double)a_numcls);
        atomicAdd(&blk[1],  (double)a_mgn);
        atomicAdd(&blk[2],  (double)a_regl);
        atomicAdd(&blk[3],  (double)a_numreg);
        atomicAdd(&blk[4],  (double)a6x);
        atomicAdd(&blk[5],  (double)a6y);
        atomicAdd(&blk[6],  (double)f6x);
        atomicAdd(&blk[7],  (double)f6y);
        atomicAdd(&blk[8],  (double)a1x);
        atomicAdd(&blk[9],  (double)a1y);
        atomicAdd(&blk[10], (double)f1x);
        atomicAdd(&blk[11], (double)f1y);
    }
    __syncthreads();
    if (threadIdx.x < 12) {
        atomicAdd(&g_acc[threadIdx.x], blk[threadIdx.x]);
        __threadfence();
    }
    __syncthreads();

    if (threadIdx.x == 0) {
        unsigned done = atomicAdd(&g_done, 1u);
        if (done == GRID - 1) {
            __threadfence();
            double acc[12];
#pragma unroll
            for (int i = 0; i < 12; i++) acc[i] = *((volatile double*)&g_acc[i]);

            double num_cls  = acc[0];
            double mgn_sum  = acc[1];
            double reg_loss = acc[2];
            double num_reg  = acc[3];
            double cls_loss = 0.2 * num_cls - mgn_sum;
            double loss = cls_loss / (num_cls + 1e-10) + reg_loss / (num_reg + 1e-10);
            out[0]  = (float)loss;
            out[1]  = (float)cls_loss;
            out[2]  = (float)num_cls;
            out[3]  = (float)reg_loss;
            out[4]  = (float)num_reg;
            out[5]  = (float)acc[4];
            out[6]  = (float)acc[5];
            out[7]  = (float)acc[6];
            out[8]  = (float)acc[7];
            out[9]  = (float)(6.0 * (double)B_ROWS * 30.0);
            out[10] = (float)(6.0 * (double)B_ROWS);
            out[11] = (float)acc[8];
            out[12] = (float)acc[9];
            out[13] = (float)acc[10];
            out[14] = (float)acc[11];
            out[15] = (float)((double)B_ROWS * 30.0);
            out[16] = (float)B_ROWS;

#pragma unroll
            for (int i = 0; i < 12; i++) *((volatile double*)&g_acc[i]) = 0.0;
            __threadfence();
            atomicExch(&g_done, 0u);
        }
    }
}

extern "C" void kernel_launch(void* const* d_in, const int* in_sizes, int n_in,
                              void* d_out, int out_size) {
    const float* reg = nullptr;
    const float* cls = nullptr;
    const float* gt  = nullptr;
    const void*  has = nullptr;
    for (int i = 0; i < n_in; i++) {
        long long n = in_sizes[i];
        if (n == (long long)B_ROWS * NM * NP * 2)      reg = (const float*)d_in[i];
        else if (n == (long long)B_ROWS * NP * 2)      gt  = (const float*)d_in[i];
        else if (n == (long long)B_ROWS * NP)          has = d_in[i];
        else if (n == (long long)B_ROWS * NM)          cls = (const float*)d_in[i];
    }
    float* out = (float*)d_out;

    loss_main<<<GRID, 256>>>(reg, cls, gt, has, out);
}